// round 9
// baseline (speedup 1.0000x reference)
#include <cuda_runtime.h>
#include <cuda_fp16.h>
#include <cstdint>

#define VOCAB 50257
#define FEAT  512
#define EPS   1e-12f

// Precomputed normalized table in fp16: 50257*512*2 B = 51.5 MB (L2-resident).
__device__ __half g_nt[(size_t)VOCAB * FEAT];

// ---------------------------------------------------------------------------
// Kernel 1: build normalized table. VT=32 vocab entries per block. (unchanged)
// ---------------------------------------------------------------------------
#define VT 32
#define SSTR 514   // halves per shared row; 257 half2 stride (odd) -> conflict-free

__global__ __launch_bounds__(512) void build_nt_kernel(
    const float* __restrict__ W, const float* __restrict__ b)
{
    __shared__ __half sh[VT * SSTR];   // 32896 B
    __shared__ float  shb[FEAT];       // 2048 B

    const int tid  = threadIdx.x;
    const int w    = tid >> 5;         // 0..15
    const int lane = tid & 31;
    const int v0   = blockIdx.x * VT;

    shb[tid] = __ldg(&b[tid]);
    __syncthreads();

    const int v = v0 + lane;
    const bool vok = (v < VOCAB);
    const float* __restrict__ Wp = W + v;

    float val[16];
    #pragma unroll
    for (int half_ = 0; half_ < 2; half_++) {
        const int itbase = half_ * 16;
        #pragma unroll
        for (int j = 0; j < 16; j++) {
            const int f = w + 16 * (itbase + j);
            val[j] = vok ? __ldcs(&Wp[(size_t)f * VOCAB]) : 0.0f;
        }
        #pragma unroll
        for (int j = 0; j < 16; j++) {
            const int f = w + 16 * (itbase + j);
            sh[(size_t)lane * SSTR + f] = __float2half_rn(val[j] + shb[f]);
        }
    }
    __syncthreads();

    #pragma unroll
    for (int rr = 0; rr < 2; rr++) {
        const int r  = 2 * w + rr;
        const int vr = v0 + r;
        if (vr >= VOCAB) continue;

        const __half2* row = (const __half2*)(sh + (size_t)r * SSTR);

        float s = 0.0f;
        float2 fv[8];
        #pragma unroll
        for (int k = 0; k < 8; k++) {
            fv[k] = __half22float2(row[lane + 32 * k]);
            s = fmaf(fv[k].x, fv[k].x, s);
            s = fmaf(fv[k].y, fv[k].y, s);
        }
        #pragma unroll
        for (int off = 16; off > 0; off >>= 1)
            s += __shfl_xor_sync(0xFFFFFFFFu, s, off);

        const float rinv = 1.0f / fmaxf(sqrtf(s), EPS);

        __half2* dst = (__half2*)(g_nt + (size_t)vr * FEAT);
        #pragma unroll
        for (int k = 0; k < 8; k++) {
            float2 p = make_float2(fv[k].x * rinv, fv[k].y * rinv);
            dst[lane + 32 * k] = __float22half2_rn(p);
        }
    }
}

// ---------------------------------------------------------------------------
// Kernel 2: gather v4. 2 tokens/warp, ids staged in shared.
// Table loads upgraded to uint4 (16 B): 2 LDG.128 per token per lane instead
// of 4 LDG.64 — same bytes/sectors, half the load-issue slots and L1tex
// wavefronts. Payload = 4 uint4 = 16 regs (below ptxas's serialization
// threshold observed in R5).
// ---------------------------------------------------------------------------
__global__ __launch_bounds__(512) void gather_kernel(
    const int* __restrict__ ids, float* __restrict__ out, int ntok)
{
    __shared__ int sh_ids[32];

    const int tid  = threadIdx.x;
    const int w    = tid >> 5;
    const int lane = tid & 31;
    const int base = blockIdx.x * 32;

    if (tid < 32) {
        const int t = base + tid;
        sh_ids[tid] = (t < ntok) ? __ldg(&ids[t]) : 0;
    }
    __syncthreads();

    const int id0 = sh_ids[2 * w];
    const int id1 = sh_ids[2 * w + 1];
    const uint4* __restrict__ s0 = (const uint4*)(g_nt + (size_t)id0 * FEAT);
    const uint4* __restrict__ s1 = (const uint4*)(g_nt + (size_t)id1 * FEAT);

    // 4 independent 16B loads in flight (full rows: 64 uint4 per row).
    uint4 u[2][2];
    #pragma unroll
    for (int k = 0; k < 2; k++) u[0][k] = __ldg(&s0[lane + 32 * k]);
    #pragma unroll
    for (int k = 0; k < 2; k++) u[1][k] = __ldg(&s1[lane + 32 * k]);

    const int t0 = base + 2 * w;
    #pragma unroll
    for (int tk = 0; tk < 2; tk++) {
        const int t = t0 + tk;
        if (t >= ntok) break;
        float4* __restrict__ dst = (float4*)(out + (size_t)t * FEAT);
        #pragma unroll
        for (int k = 0; k < 2; k++) {
            // Each uint4 = 8 halves -> two float4 outputs.
            __half2 h0 = *reinterpret_cast<__half2*>(&u[tk][k].x);
            __half2 h1 = *reinterpret_cast<__half2*>(&u[tk][k].y);
            __half2 h2 = *reinterpret_cast<__half2*>(&u[tk][k].z);
            __half2 h3 = *reinterpret_cast<__half2*>(&u[tk][k].w);
            float2 f0 = __half22float2(h0);
            float2 f1 = __half22float2(h1);
            float2 f2 = __half22float2(h2);
            float2 f3 = __half22float2(h3);
            // uint4 index (lane + 32k) covers halves [8*(lane+32k), +8)
            // = float4 output indices 2*(lane+32k) and 2*(lane+32k)+1.
            const int o = 2 * (lane + 32 * k);
            __stcs(&dst[o],     make_float4(f0.x, f0.y, f1.x, f1.y));
            __stcs(&dst[o + 1], make_float4(f2.x, f2.y, f3.x, f3.y));
        }
    }
}

// ---------------------------------------------------------------------------
// Launch
//   d_in[0] = token_ids int32 [32*4096]
//   d_in[1] = W float32 [512*50257]
//   d_in[2] = b float32 [512]
//   d_out   = float32 [32*4096*512]
// ---------------------------------------------------------------------------
extern "C" void kernel_launch(void* const* d_in, const int* in_sizes, int n_in,
                              void* d_out, int out_size)
{
    const int*   ids = (const int*)d_in[0];
    const float* W   = (const float*)d_in[1];
    const float* b   = (const float*)d_in[2];
    float*       out = (float*)d_out;

    const int ntok = in_sizes[0];   // 131072

    const int nt_blocks = (VOCAB + VT - 1) / VT;   // 1571
    build_nt_kernel<<<nt_blocks, 512>>>(W, b);

    const int g_blocks = (ntok + 31) / 32;         // 4096
    gather_kernel<<<g_blocks, 512>>>(ids, out, ntok);
}

// round 10
// speedup vs baseline: 1.3968x; 1.3968x over previous
#include <cuda_runtime.h>
#include <cuda_fp16.h>
#include <cstdint>

#define VOCAB 50257
#define FEAT  512
#define EPS   1e-12f

// Precomputed normalized table in fp16: 50257*512*2 B = 51.5 MB (L2-resident).
__device__ __half g_nt[(size_t)VOCAB * FEAT];

// ---------------------------------------------------------------------------
// Kernel 1: build normalized table. VT=32 vocab entries per block.
//   Load : warp w owns feature PAIRS p = w + 16*jj (jj=0..15), i.e. features
//          2p and 2p+1. Two 128B coalesced loads per pair, batched 16 LDGs
//          deep in registers, then packed to half2 and stored with ONE
//          full-width 128B STS per pair (vs 2B/lane scattered stores before).
//   Tile : sh2[vocab_lane][pair], pair-stride 257 (odd) -> conflict-free for
//          both the transposed stores (lane stride 257 banks ≡ 1) and the
//          norm-phase row reads. Same layout the norm phase already used.
//   Norm : warp w reduces vocab rows 2w / 2w+1, writes fp16 rows coalesced.
// ---------------------------------------------------------------------------
#define VT 32
#define S2 257   // half2 per shared row (stride); odd -> bank-conflict-free

__global__ __launch_bounds__(512) void build_nt_kernel(
    const float* __restrict__ W, const float* __restrict__ b)
{
    __shared__ __half2 sh2[VT * S2];   // 32*257*4 = 32896 B
    __shared__ float   shb[FEAT];      // 2048 B

    const int tid  = threadIdx.x;
    const int w    = tid >> 5;         // 0..15
    const int lane = tid & 31;
    const int v0   = blockIdx.x * VT;

    shb[tid] = __ldg(&b[tid]);
    __syncthreads();

    const int v = v0 + lane;
    const bool vok = (v < VOCAB);
    const float* __restrict__ Wp = W + v;

    // 16 pairs per warp, two 8-pair batches (16 LDGs in flight per batch).
    float a0[8], a1[8];
    #pragma unroll
    for (int half_ = 0; half_ < 2; half_++) {
        const int pb = half_ * 8;
        #pragma unroll
        for (int j = 0; j < 8; j++) {
            const int p = w + 16 * (pb + j);          // pair index 0..255
            a0[j] = vok ? __ldcs(&Wp[(size_t)(2 * p)     * VOCAB]) : 0.0f;
            a1[j] = vok ? __ldcs(&Wp[(size_t)(2 * p + 1) * VOCAB]) : 0.0f;
        }
        #pragma unroll
        for (int j = 0; j < 8; j++) {
            const int p = w + 16 * (pb + j);
            float2 pv = make_float2(a0[j] + shb[2 * p], a1[j] + shb[2 * p + 1]);
            sh2[(size_t)lane * S2 + p] = __float22half2_rn(pv);
        }
    }
    __syncthreads();

    // Each warp handles 2 vocab rows: r = 2w, 2w+1.
    #pragma unroll
    for (int rr = 0; rr < 2; rr++) {
        const int r  = 2 * w + rr;
        const int vr = v0 + r;
        if (vr >= VOCAB) continue;

        const __half2* row = sh2 + (size_t)r * S2;

        float s = 0.0f;
        float2 fv[8];
        #pragma unroll
        for (int k = 0; k < 8; k++) {
            fv[k] = __half22float2(row[lane + 32 * k]);
            s = fmaf(fv[k].x, fv[k].x, s);
            s = fmaf(fv[k].y, fv[k].y, s);
        }
        #pragma unroll
        for (int off = 16; off > 0; off >>= 1)
            s += __shfl_xor_sync(0xFFFFFFFFu, s, off);

        const float rinv = 1.0f / fmaxf(sqrtf(s), EPS);

        __half2* dst = (__half2*)(g_nt + (size_t)vr * FEAT);
        #pragma unroll
        for (int k = 0; k < 8; k++) {
            float2 p = make_float2(fv[k].x * rinv, fv[k].y * rinv);
            dst[lane + 32 * k] = __float22half2_rn(p);
        }
    }
}

// ---------------------------------------------------------------------------
// Kernel 2: gather — EXACT R8 version (proven 51.6us, ~97% of write-mix
// bandwidth ceiling). LDG.64 table loads are load-width-matched to the
// fp16->fp32 expansion so every STG.128 wavefront is perfectly contiguous.
// DO NOT change the load width (R9 lesson).
// ---------------------------------------------------------------------------
__global__ __launch_bounds__(512) void gather_kernel(
    const int* __restrict__ ids, float* __restrict__ out, int ntok)
{
    __shared__ int sh_ids[32];

    const int tid  = threadIdx.x;
    const int w    = tid >> 5;
    const int lane = tid & 31;
    const int base = blockIdx.x * 32;

    if (tid < 32) {
        const int t = base + tid;
        sh_ids[tid] = (t < ntok) ? __ldg(&ids[t]) : 0;
    }
    __syncthreads();

    const int id0 = sh_ids[2 * w];
    const int id1 = sh_ids[2 * w + 1];
    const uint2* __restrict__ s0 = (const uint2*)(g_nt + (size_t)id0 * FEAT);
    const uint2* __restrict__ s1 = (const uint2*)(g_nt + (size_t)id1 * FEAT);

    uint2 u[2][4];
    #pragma unroll
    for (int k = 0; k < 4; k++) u[0][k] = __ldg(&s0[lane + 32 * k]);
    #pragma unroll
    for (int k = 0; k < 4; k++) u[1][k] = __ldg(&s1[lane + 32 * k]);

    const int t0 = base + 2 * w;
    #pragma unroll
    for (int tk = 0; tk < 2; tk++) {
        const int t = t0 + tk;
        if (t >= ntok) break;
        float4* __restrict__ dst = (float4*)(out + (size_t)t * FEAT);
        #pragma unroll
        for (int k = 0; k < 4; k++) {
            __half2 h0 = *reinterpret_cast<__half2*>(&u[tk][k].x);
            __half2 h1 = *reinterpret_cast<__half2*>(&u[tk][k].y);
            float2 f0 = __half22float2(h0);
            float2 f1 = __half22float2(h1);
            __stcs(&dst[lane + 32 * k], make_float4(f0.x, f0.y, f1.x, f1.y));
        }
    }
}

// ---------------------------------------------------------------------------
// Launch
//   d_in[0] = token_ids int32 [32*4096]
//   d_in[1] = W float32 [512*50257]
//   d_in[2] = b float32 [512]
//   d_out   = float32 [32*4096*512]
// ---------------------------------------------------------------------------
extern "C" void kernel_launch(void* const* d_in, const int* in_sizes, int n_in,
                              void* d_out, int out_size)
{
    const int*   ids = (const int*)d_in[0];
    const float* W   = (const float*)d_in[1];
    const float* b   = (const float*)d_in[2];
    float*       out = (float*)d_out;

    const int ntok = in_sizes[0];   // 131072

    const int nt_blocks = (VOCAB + VT - 1) / VT;   // 1571
    build_nt_kernel<<<nt_blocks, 512>>>(W, b);

    const int g_blocks = (ntok + 31) / 32;         // 4096
    gather_kernel<<<g_blocks, 512>>>(ids, out, ntok);
}